// round 11
// baseline (speedup 1.0000x reference)
#include <cuda_runtime.h>
#include <cstdint>

// Haar (db1) 2-D DWT on (B=16, C=3, H=1024, W=1024) fp32.
// Output: concatenated planes [cA | cH | cV | cD], each (16,3,512,512).
//
// R11: persistent grid-stride loop. Fixed grid = 148 SMs x 8 CTAs (one full
// residency wave, 32 regs, 256 thr). Each thread processes ~10 tiles of
// 2 rows x 8 cols (MLP=4 __ldcs loads, default stores). Removes CTA
// launch/drain churn: loads of iteration k+1 issue right behind the
// fire-and-forget stores of iteration k, keeping per-warp loads in flight
// continuously instead of decaying to zero at every CTA tail.

static constexpr int Bc    = 16 * 3;        // images
static constexpr int H     = 1024;
static constexpr int W     = 1024;
static constexpr int H2    = H / 2;         // 512
static constexpr int W2    = W / 2;         // 512
static constexpr int W8    = W / 8;         // 8-col tiles per row = 128
static constexpr int PLANE = Bc * H2 * W2;  // elements per output plane
static constexpr int TOTAL = Bc * H2 * W8;  // thread-tiles = 3,145,728

static constexpr int BLOCK = 256;
static constexpr int GRID  = 148 * 8;       // one full residency wave

__global__ __launch_bounds__(BLOCK, 8)
void haar_dwt_kernel(const float* __restrict__ x, float* __restrict__ out) {
    const int stride = GRID * BLOCK;
    for (int t = blockIdx.x * BLOCK + threadIdx.x; t < TOTAL; t += stride) {
        int j  = t & (W8 - 1);          // 8-col tile index
        int r  = t >> 7;                // / W8
        int i  = r & (H2 - 1);          // output row
        int bc = r >> 9;                // / H2

        const float4* row0 = reinterpret_cast<const float4*>(
            x + (size_t)bc * H * W + (size_t)(2 * i) * W) + 2 * j;
        const float4* row1 = row0 + (W / 4);

        // front-batch all 4 loads (MLP=4), streaming/evict-first (no reuse)
        float4 a0 = __ldcs(row0);
        float4 a1 = __ldcs(row0 + 1);
        float4 b0 = __ldcs(row1);
        float4 b1 = __ldcs(row1 + 1);

        float s0 = a0.x + a0.y, d0 = a0.x - a0.y;
        float s1 = b0.x + b0.y, d1 = b0.x - b0.y;
        float s2 = a0.z + a0.w, d2 = a0.z - a0.w;
        float s3 = b0.z + b0.w, d3 = b0.z - b0.w;
        float s4 = a1.x + a1.y, d4 = a1.x - a1.y;
        float s5 = b1.x + b1.y, d5 = b1.x - b1.y;
        float s6 = a1.z + a1.w, d6 = a1.z - a1.w;
        float s7 = b1.z + b1.w, d7 = b1.z - b1.w;

        float4 cA = make_float4((s0 + s1) * 0.5f, (s2 + s3) * 0.5f,
                                (s4 + s5) * 0.5f, (s6 + s7) * 0.5f);
        float4 cH = make_float4((s0 - s1) * 0.5f, (s2 - s3) * 0.5f,
                                (s4 - s5) * 0.5f, (s6 - s7) * 0.5f);
        float4 cV = make_float4((d0 + d1) * 0.5f, (d2 + d3) * 0.5f,
                                (d4 + d5) * 0.5f, (d6 + d7) * 0.5f);
        float4 cD = make_float4((d0 - d1) * 0.5f, (d2 - d3) * 0.5f,
                                (d4 - d5) * 0.5f, (d6 - d7) * 0.5f);

        size_t o = (size_t)bc * H2 * W2 + (size_t)i * W2 + 4 * j;  // 16B aligned
        *reinterpret_cast<float4*>(out + o)                     = cA;
        *reinterpret_cast<float4*>(out + PLANE + o)             = cH;
        *reinterpret_cast<float4*>(out + 2 * (size_t)PLANE + o) = cV;
        *reinterpret_cast<float4*>(out + 3 * (size_t)PLANE + o) = cD;
    }
}

extern "C" void kernel_launch(void* const* d_in, const int* in_sizes, int n_in,
                              void* d_out, int out_size) {
    const float* x  = (const float*)d_in[0];
    float* out      = (float*)d_out;
    haar_dwt_kernel<<<GRID, BLOCK>>>(x, out);
}

// round 13
// speedup vs baseline: 1.1106x; 1.1106x over previous
#include <cuda_runtime.h>
#include <cstdint>

// Haar (db1) 2-D DWT on (B=16, C=3, H=1024, W=1024) fp32.
// Output: concatenated planes [cA | cH | cV | cD], each (16,3,512,512).
//
// FINAL (R2 config, best measured): one thread = 4 adjacent 2x2 blocks
// (2 input rows x 8 cols). 4 front-batched __ldcs float4 loads (MLP=4),
// one __stcs float4 store per output plane. 32 regs, 256-thr CTAs.
//
// Measured at 6260 GB/s — the full-chip LTS throughput ceiling
// (B300_MICROARCH: ~6300 B/cyc, path-independent, saturates before HBM).
// Seven variants (store width/policy, cache hints, tile depth, CTA size,
// persistent loop) all land in 6130-6260 GB/s; this config had the best
// kernel duration. Traffic (402 MB) is irreducible for this transform.

static constexpr int Bc    = 16 * 3;        // images
static constexpr int H     = 1024;
static constexpr int W     = 1024;
static constexpr int H2    = H / 2;         // 512
static constexpr int W2    = W / 2;         // 512
static constexpr int W8    = W / 8;         // 8-col tiles per row = 128
static constexpr int PLANE = Bc * H2 * W2;  // elements per output plane

__global__ __launch_bounds__(256, 8)
void haar_dwt_kernel(const float* __restrict__ x, float* __restrict__ out) {
    int t = blockIdx.x * blockDim.x + threadIdx.x;
    // t in [0, Bc*H2*W8)
    int j  = t & (W8 - 1);          // 8-col tile index
    int r  = t >> 7;                // / W8
    int i  = r & (H2 - 1);          // output row
    int bc = r >> 9;                // / H2

    const float4* row0 = reinterpret_cast<const float4*>(
        x + (size_t)bc * H * W + (size_t)(2 * i) * W) + 2 * j;
    const float4* row1 = row0 + (W / 4);

    // front-batch all 4 loads (MLP=4), streaming/evict-first (no reuse)
    float4 a0 = __ldcs(row0);       // row 2i,   cols 8j..8j+3
    float4 a1 = __ldcs(row0 + 1);   // row 2i,   cols 8j+4..8j+7
    float4 b0 = __ldcs(row1);       // row 2i+1, cols 8j..8j+3
    float4 b1 = __ldcs(row1 + 1);   // row 2i+1, cols 8j+4..8j+7

    float s0 = a0.x + a0.y, d0 = a0.x - a0.y;
    float s1 = b0.x + b0.y, d1 = b0.x - b0.y;
    float s2 = a0.z + a0.w, d2 = a0.z - a0.w;
    float s3 = b0.z + b0.w, d3 = b0.z - b0.w;
    float s4 = a1.x + a1.y, d4 = a1.x - a1.y;
    float s5 = b1.x + b1.y, d5 = b1.x - b1.y;
    float s6 = a1.z + a1.w, d6 = a1.z - a1.w;
    float s7 = b1.z + b1.w, d7 = b1.z - b1.w;

    float4 cA = make_float4((s0 + s1) * 0.5f, (s2 + s3) * 0.5f,
                            (s4 + s5) * 0.5f, (s6 + s7) * 0.5f);
    float4 cH = make_float4((s0 - s1) * 0.5f, (s2 - s3) * 0.5f,
                            (s4 - s5) * 0.5f, (s6 - s7) * 0.5f);
    float4 cV = make_float4((d0 + d1) * 0.5f, (d2 + d3) * 0.5f,
                            (d4 + d5) * 0.5f, (d6 + d7) * 0.5f);
    float4 cD = make_float4((d0 - d1) * 0.5f, (d2 - d3) * 0.5f,
                            (d4 - d5) * 0.5f, (d6 - d7) * 0.5f);

    size_t o = (size_t)bc * H2 * W2 + (size_t)i * W2 + 4 * j;  // 16B aligned
    __stcs(reinterpret_cast<float4*>(out + o),                      cA);
    __stcs(reinterpret_cast<float4*>(out + PLANE + o),              cH);
    __stcs(reinterpret_cast<float4*>(out + 2 * (size_t)PLANE + o),  cV);
    __stcs(reinterpret_cast<float4*>(out + 3 * (size_t)PLANE + o),  cD);
}

extern "C" void kernel_launch(void* const* d_in, const int* in_sizes, int n_in,
                              void* d_out, int out_size) {
    const float* x  = (const float*)d_in[0];
    float* out      = (float*)d_out;

    int total_threads = Bc * H2 * W8;          // 3,145,728
    int block = 256;
    int grid  = total_threads / block;         // 12288
    haar_dwt_kernel<<<grid, block>>>(x, out);
}